// round 1
// baseline (speedup 1.0000x reference)
#include <cuda_runtime.h>
#include <math_constants.h>
#include <float.h>

// AdaPool3d, K=2 (non-overlapping 2x2x2 windows)
// x:    [B=4, C=64, D=16, H=112, W=112] f32
// beta: [oD=8, oH=56, oW=56] f32
// out:  [B, C, oD=8, oH=56, oW=56] f32

#define B_ 4
#define C_ 64
#define D_ 16
#define H_ 112
#define W_ 112
#define OD 8
#define OH 56
#define OW 56
#define SPATIAL (OD * OH * OW)                 // 25088
#define TOTAL (B_ * C_ * SPATIAL)              // 6,422,528
#define PLANE (H_ * W_)                        // 12544

__global__ __launch_bounds__(256, 8)
void adapool3d_kernel(const float* __restrict__ x,
                      const float* __restrict__ beta,
                      float* __restrict__ out)
{
    int n = blockIdx.x * blockDim.x + threadIdx.x;
    if (n >= TOTAL) return;

    // decompose: n = bc * SPATIAL + od*OH*OW + oh*OW + ow
    int ow = n % OW;
    int t  = n / OW;
    int oh = t % OH;
    t      = t / OH;
    int od = t % OD;
    int bc = t / OD;
    int sp = n - bc * SPATIAL;                 // beta index

    const float* p = x + ((size_t)bc * D_ + 2 * od) * PLANE
                       + (2 * oh) * W_ + 2 * ow;

    // 8-element window via 4 coalesced float2 loads
    float2 a0 = *reinterpret_cast<const float2*>(p);
    float2 a1 = *reinterpret_cast<const float2*>(p + W_);
    float2 a2 = *reinterpret_cast<const float2*>(p + PLANE);
    float2 a3 = *reinterpret_cast<const float2*>(p + PLANE + W_);

    float v[8] = {a0.x, a0.y, a1.x, a1.y, a2.x, a2.y, a3.x, a3.y};

    // window mean
    float s = 0.f;
    #pragma unroll
    for (int i = 0; i < 8; i++) s += v[i];
    float avg  = s * 0.125f;
    float avg2 = avg * avg;

    // Dice-Sorensen per element: dsc = denom>0 ? 2*v*avg/denom : 0
    float d[8];
    #pragma unroll
    for (int i = 0; i < 8; i++) {
        float den = fmaf(v[i], v[i], avg2);
        float num = 2.0f * v[i] * avg;
        d[i] = (den > 0.0f) ? __fdividef(num, den) : 0.0f;
    }

    // softmax over dsc, weighted sum of v  (EDSCW)
    float m1 = d[0];
    #pragma unroll
    for (int i = 1; i < 8; i++) m1 = fmaxf(m1, d[i]);
    float s1 = 0.f, w1 = 0.f;
    #pragma unroll
    for (int i = 0; i < 8; i++) {
        float e = __expf(d[i] - m1);
        s1 += e;
        w1 = fmaf(e, v[i], w1);
    }
    float edscw = __fdividef(w1, s1);

    // softmax over v, weighted sum of v  (SoftPool / exponential max)
    float m2 = v[0];
    #pragma unroll
    for (int i = 1; i < 8; i++) m2 = fmaxf(m2, v[i]);
    float s2 = 0.f, w2 = 0.f;
    #pragma unroll
    for (int i = 0; i < 8; i++) {
        float e = __expf(v[i] - m2);
        s2 += e;
        w2 = fmaf(e, v[i], w2);
    }
    float em = __fdividef(w2, s2);

    float b  = __ldg(beta + sp);
    float r  = b * edscw + (1.0f - b) * em;

    // jnp.nan_to_num: nan -> 0, +inf -> FLT_MAX, -inf -> -FLT_MAX
    if (!isfinite(r)) r = isnan(r) ? 0.0f : (r > 0.0f ? FLT_MAX : -FLT_MAX);

    out[n] = r;
}

extern "C" void kernel_launch(void* const* d_in, const int* in_sizes, int n_in,
                              void* d_out, int out_size)
{
    const float* x    = (const float*)d_in[0];
    const float* beta = (const float*)d_in[1];
    float* out        = (float*)d_out;

    const int threads = 256;
    const int blocks  = (TOTAL + threads - 1) / threads;  // 25088
    adapool3d_kernel<<<blocks, threads>>>(x, beta, out);
}

// round 2
// speedup vs baseline: 1.3156x; 1.3156x over previous
#include <cuda_runtime.h>
#include <math_constants.h>
#include <float.h>

// AdaPool3d, K=2 (non-overlapping 2x2x2 windows)
// x:    [B=4, C=64, D=16, H=112, W=112] f32
// beta: [oD=8, oH=56, oW=56] f32
// out:  [B, C, oD=8, oH=56, oW=56] f32

#define B_ 4
#define C_ 64
#define D_ 16
#define H_ 112
#define W_ 112
#define OD 8
#define OH 56
#define OW 56
#define SPATIAL (OD * OH * OW)                 // 25088
#define TOTAL (B_ * C_ * SPATIAL)              // 6,422,528
#define PLANE (H_ * W_)                        // 12544
#define PAIRS (TOTAL / 2)                      // 3,211,264
#define PAIRS_PER_BC (SPATIAL / 2)             // 12544
#define PW (OW / 2)                            // 28

#define LOG2E 1.4426950408889634f

__device__ __forceinline__ float ex2f(float x) {
    float r; asm("ex2.approx.f32 %0, %1;" : "=f"(r) : "f"(x)); return r;
}
__device__ __forceinline__ float frcpf(float x) {
    float r; asm("rcp.approx.f32 %0, %1;" : "=f"(r) : "f"(x)); return r;
}

// One 2x2x2 window: returns beta-blended AdaPool output.
__device__ __forceinline__ float pool_one(const float v[8], float b)
{
    // window mean
    float s = (((v[0] + v[1]) + (v[2] + v[3])) + ((v[4] + v[5]) + (v[6] + v[7])));
    float avg  = 0.125f * s;
    float avg2 = avg * avg;
    float c    = (2.0f * LOG2E) * avg;   // log2e folded into Dice numerator

    // Dice: t_i = log2e * dsc_i = (v*c) / (v^2 + avg^2)
    // den>0 guard: den==0 => num==0, so clamping den to FLT_MIN yields exact 0.
    float num[8], den[8];
    #pragma unroll
    for (int i = 0; i < 8; i++) {
        den[i] = fmaxf(fmaf(v[i], v[i], avg2), 1.1754944e-38f);
        num[i] = v[i] * c;
    }

    float t[8];
    #pragma unroll
    for (int p = 0; p < 4; p++) {        // pairwise reciprocal: 4 RCP not 8
        float d0 = den[2*p], d1 = den[2*p+1];
        float rp = frcpf(d0 * d1);
        t[2*p]   = num[2*p]   * (d1 * rp);
        t[2*p+1] = num[2*p+1] * (d0 * rp);
    }

    // Two 8-way softmax-weighted sums, no max-subtraction (args bounded):
    //   edscw = w1/s1 over exp(dsc), em = w2/s2 over exp(v)
    float s1 = 0.f, w1 = 0.f, s2 = 0.f, w2 = 0.f;
    #pragma unroll
    for (int i = 0; i < 8; i++) {
        float e1 = ex2f(t[i]);
        s1 += e1;  w1 = fmaf(e1, v[i], w1);
        float e2 = ex2f(v[i] * LOG2E);
        s2 += e2;  w2 = fmaf(e2, v[i], w2);
    }

    // r = b*w1/s1 + (1-b)*w2/s2 = (b*w1*s2 + (1-b)*w2*s1) * rcp(s1*s2)
    float rp = frcpf(s1 * s2);
    float r  = (b * w1 * s2 + (1.0f - b) * (w2 * s1)) * rp;

    // jnp.nan_to_num (cheap guard; normally a no-op)
    if (!isfinite(r)) r = isnan(r) ? 0.0f : (r > 0.0f ? FLT_MAX : -FLT_MAX);
    return r;
}

__global__ __launch_bounds__(256)
void adapool3d_kernel(const float* __restrict__ x,
                      const float* __restrict__ beta,
                      float* __restrict__ out)
{
    int n = blockIdx.x * 256 + threadIdx.x;     // pair index; grid covers PAIRS exactly

    // n = bc*PAIRS_PER_BC + od*(OH*PW) + oh*PW + pw
    int pw = n % PW;
    int t  = n / PW;
    int oh = t % OH;
    t      = t / OH;
    int od = t % OD;
    int bc = t / OD;
    int sp = (n - bc * PAIRS_PER_BC) * 2;       // spatial index of first output

    const float* p = x + ((size_t)bc * D_ + 2 * od) * PLANE
                       + (2 * oh) * W_ + 4 * pw;

    // Two adjacent 2x2x2 windows via 4 x LDG.128 (all 16B-aligned)
    float4 r0 = *reinterpret_cast<const float4*>(p);
    float4 r1 = *reinterpret_cast<const float4*>(p + W_);
    float4 r2 = *reinterpret_cast<const float4*>(p + PLANE);
    float4 r3 = *reinterpret_cast<const float4*>(p + PLANE + W_);

    float vA[8] = {r0.x, r0.y, r1.x, r1.y, r2.x, r2.y, r3.x, r3.y};
    float vB[8] = {r0.z, r0.w, r1.z, r1.w, r2.z, r2.w, r3.z, r3.w};

    float2 bb = *reinterpret_cast<const float2*>(beta + sp);

    float oA = pool_one(vA, bb.x);
    float oB = pool_one(vB, bb.y);

    *reinterpret_cast<float2*>(out + (size_t)bc * SPATIAL + sp) = make_float2(oA, oB);
}

extern "C" void kernel_launch(void* const* d_in, const int* in_sizes, int n_in,
                              void* d_out, int out_size)
{
    const float* x    = (const float*)d_in[0];
    const float* beta = (const float*)d_in[1];
    float* out        = (float*)d_out;

    const int threads = 256;
    const int blocks  = PAIRS / threads;        // 12544, exact
    adapool3d_kernel<<<blocks, threads>>>(x, beta, out);
}